// round 11
// baseline (speedup 1.0000x reference)
#include <cuda_runtime.h>

// Locally-connected 2D: out[oy,ox] = sum_{ky,kx} x[oy+ky, ox+kx] * W[oy,ox,ky,kx]
// x: [450,450] f32, W: [436,436,15,15] f32 (171 MB streamed once), out: [436,436].
//
// Theory: runtime == L1tex wavefront service time. The scattered per-lane x
// LDGs generate ~30-40 wavefronts/pixel (vs W's ~16). Fix: block = 8
// consecutive pixels of one row; stage the shared 15x22 x-tile to smem once
// (~2.5 wf/pixel), serve x via LDS (smem crossbar, off the L1tex global
// path). W path identical to the best-measured kernel: warp-per-pixel,
// 8 scalar LDG.32, __ldcs, short L2 prefetch, dual accumulators.

#define IN_H 450
#define IN_W 450
#define KH 15
#define KW 15
#define OH 436
#define OW 436
#define KSIZE 225
#define NPIX (OH * OW)     // 190096
#define PXB 8              // pixels per block (one warp each)
#define XC 22              // x-tile cols = PXB + KW - 1
#define XTOT (KH * XC)     // 330 floats
#define PFD 96             // W prefetch distance in pixels

__global__ __launch_bounds__(256)
void lc2d_kernel(const float* __restrict__ x,
                 const float* __restrict__ W,
                 float* __restrict__ out)
{
    __shared__ float Xs[XTOT];

    const int tid  = threadIdx.x;
    const int lane = tid & 31;
    const int wrp  = tid >> 5;            // warp index = pixel within block
    const int row  = blockIdx.y;          // output row
    const int ox0  = blockIdx.x * PXB;    // first output col of this block

    // ---- Stage x tile: rows [row, row+15), cols [ox0, ox0+22) ----
#pragma unroll
    for (int i = tid; i < XTOT; i += 256) {
        const int r = i / XC;
        const int c = i - r * XC;
        const int gc = ox0 + c;
        Xs[i] = (gc < IN_W) ? __ldg(x + (row + r) * IN_W + gc) : 0.0f;
    }
    __syncthreads();

    const int px = ox0 + wrp;
    if (px >= OW) return;
    const int pix = row * OW + px;

    const float* wp = W + (size_t)pix * KSIZE + lane;

    // L2 prefetch of the W block PFD pixels ahead (8 lanes x 128B cover 900B).
    if (lane < 8 && pix + PFD < NPIX) {
        const char* pf = (const char*)(W + (size_t)(pix + PFD) * KSIZE) + lane * 128;
        asm volatile("prefetch.global.L2 [%0];" :: "l"(pf));
    }

    // Per-lane smem offsets for k = lane + 32*i: (k/15)*XC + k%15 + wrp.
    int o0, o1, o2, o3, o4, o5, o6;
    {
        int k, ky;
        k = lane;       ky = k / KW; o0 = ky * XC + (k - ky * KW) + wrp;
        k = lane + 32;  ky = k / KW; o1 = ky * XC + (k - ky * KW) + wrp;
        k = lane + 64;  ky = k / KW; o2 = ky * XC + (k - ky * KW) + wrp;
        k = lane + 96;  ky = k / KW; o3 = ky * XC + (k - ky * KW) + wrp;
        k = lane + 128; ky = k / KW; o4 = ky * XC + (k - ky * KW) + wrp;
        k = lane + 160; ky = k / KW; o5 = ky * XC + (k - ky * KW) + wrp;
        k = lane + 192; ky = k / KW; o6 = ky * XC + (k - ky * KW) + wrp;
    }

    // Batch W loads (independent -> max MLP), x from smem, then FMAs.
    const float w0 = __ldcs(wp);
    const float w1 = __ldcs(wp + 32);
    const float w2 = __ldcs(wp + 64);
    const float w3 = __ldcs(wp + 96);
    const float w4 = __ldcs(wp + 128);
    const float w5 = __ldcs(wp + 160);
    const float w6 = __ldcs(wp + 192);

    const float v0 = Xs[o0];
    const float v1 = Xs[o1];
    const float v2 = Xs[o2];
    const float v3 = Xs[o3];
    const float v4 = Xs[o4];
    const float v5 = Xs[o5];
    const float v6 = Xs[o6];

    float s0 = w0 * v0;
    float s1 = w1 * v1;
    s0 = fmaf(w2, v2, s0);
    s1 = fmaf(w3, v3, s1);
    s0 = fmaf(w4, v4, s0);
    s1 = fmaf(w5, v5, s1);
    s0 = fmaf(w6, v6, s0);

    // Tail element k = 224 (ky=14, kx=14): lane 0 only.
    if (lane == 0)
        s1 = fmaf(__ldcs(wp + 224), Xs[14 * XC + 14 + wrp], s1);

    float sum = s0 + s1;
#pragma unroll
    for (int off = 16; off > 0; off >>= 1)
        sum += __shfl_down_sync(0xffffffffu, sum, off);

    if (lane == 0)
        out[pix] = sum;
}

extern "C" void kernel_launch(void* const* d_in, const int* in_sizes, int n_in,
                              void* d_out, int out_size)
{
    const float* x = (const float*)d_in[0];
    const float* W = (const float*)d_in[1];
    float* out = (float*)d_out;

    dim3 grid((OW + PXB - 1) / PXB, OH);   // 55 x 436 = 23980 blocks
    lc2d_kernel<<<grid, 256>>>(x, W, out);
}